// round 13
// baseline (speedup 1.0000x reference)
#include <cuda_runtime.h>
#include <cuda_bf16.h>
#include <cstdint>

// Problem dims
#define Tt 128
#define Bb 32
#define Ii 256
#define Hh 1024
#define Oo 128
#define BH (Bb*Hh)      // 32768 floats per timestep of h
#define MROWS (Tt*Bb)   // 4096 flattened (t,b) rows

// Scratch (device globals: no allocations allowed)
__device__ float g_xin[Tt*BH];        // X @ W_in^T, [T,B,H]
__device__ float g_h[(Tt+1)*BH];      // h_all[0..T], [T+1,B,H]
__device__ float g_err[MROWS*Oo];     // err, [T*B,O]
__device__ float g_c[MROWS*Hh];       // c, then (in-place) a, [T*B,H]
__device__ unsigned g_bars[128];      // 4 group barriers, stride 32 (separate lines)

// ---------------------------------------------------------------------------
// Packed fp32x2 FMA (Blackwell FFMA2: 2 fp32 FMAs per instruction)
// ---------------------------------------------------------------------------
__device__ __forceinline__ unsigned long long ffma2_(unsigned long long a,
                                                     unsigned long long b,
                                                     unsigned long long c)
{
    unsigned long long d;
    asm("fma.rn.f32x2 %0, %1, %2, %3;" : "=l"(d) : "l"(a), "l"(b), "l"(c));
    return d;
}
union F4U { float4 f; unsigned long long u[2]; float s[4]; };
union U2F { unsigned long long u; float2 f; };

// ---------------------------------------------------------------------------
// cp.async helper (LDGSTS .cg: bypasses L1 -> coherent with other SMs' stores)
// ---------------------------------------------------------------------------
__device__ __forceinline__ void cp16(uint32_t saddr, const void* gptr)
{
    asm volatile("cp.async.cg.shared.global [%0], [%1], 16;\n" :: "r"(saddr), "l"(gptr));
}

// ---------------------------------------------------------------------------
// zero_kernel: grid-stride zero of split-K targets + barrier reset
// init_kernel: copy h0 into g_h[0]
// ---------------------------------------------------------------------------
__global__ void zero_kernel(float* __restrict__ p, int n)
{
    int i = blockIdx.x * blockDim.x + threadIdx.x;
    if (i < 128) g_bars[i] = 0u;
    for (; i < n; i += gridDim.x * blockDim.x) p[i] = 0.f;
}

__global__ void init_kernel(const float* __restrict__ h0)
{
    int i = blockIdx.x * blockDim.x + threadIdx.x;
    if (i < BH) g_h[i] = h0[i];
}

// ---------------------------------------------------------------------------
// Forward scan: h_{t+1} = tanh(xin_t + h_t @ W_hh^T)
// (R9 configuration — best measured: 550us. 4 groups x 32 slices, 256 thr.)
// group g owns batches [8g,8g+8); CTA slice s owns rows [32s,32s+32).
// W_hh in registers: warp w (0..7) = k-slice [128w,128w+128); lane jl = row.
// ---------------------------------------------------------------------------
__global__ void __launch_bounds__(256, 1) scan_fwd(const float* __restrict__ Whh,
                                                   float* __restrict__ hf_out)
{
    __shared__ float hs[8 * Hh];          // 32KB staged h for this group's batches
    __shared__ float part[8 * 8 * 32];    // 8KB partials [kslice][b][j]

    int tid = threadIdx.x;
    int grp = blockIdx.x >> 5;            // batch group 0..3
    int sl  = blockIdx.x & 31;            // row slice 0..31
    int jbase = sl * 32;
    int bbase = grp * 8;

    int w  = tid >> 5;                    // k-slice == warp id (0..7)
    int jl = tid & 31;                    // row within slice (lane)
    int kbase = w * 128;

    // One-time: W[jbase+jl][kbase .. kbase+128) into 64 f32x2 registers
    unsigned long long wreg[64];
    {
        const float* wr = Whh + (size_t)(jbase + jl) * Hh + kbase;
        #pragma unroll
        for (int i = 0; i < 32; ++i) {
            F4U v; v.f = *(const float4*)&wr[i * 4];
            wreg[2 * i] = v.u[0]; wreg[2 * i + 1] = v.u[1];
        }
    }

    int eb = tid >> 5;                    // epilogue batch (0..7)
    int ej = tid & 31;                    // epilogue row within slice
    uint32_t hs_base = (uint32_t)__cvta_generic_to_shared(hs);
    unsigned* bar = &g_bars[grp * 32];

    for (int t = 0; t < Tt; ++t) {
        const float* hcur = g_h + (size_t)t * BH + (size_t)bbase * Hh;

        // Stage 8*1024 floats = 2048 float4 over 256 threads; 2 commit groups
        #pragma unroll
        for (int r = 0; r < 4; ++r) {
            int f = tid + (r << 8);
            cp16(hs_base + (f << 4), hcur + (f << 2));
        }
        asm volatile("cp.async.commit_group;\n");
        #pragma unroll
        for (int r = 4; r < 8; ++r) {
            int f = tid + (r << 8);
            cp16(hs_base + (f << 4), hcur + (f << 2));
        }
        asm volatile("cp.async.commit_group;\n");

        float accx = g_xin[(size_t)t * BH + (size_t)(bbase + eb) * Hh + jbase + ej];

        unsigned long long acc0[8], acc1[8];   // 2 chains per batch
        #pragma unroll
        for (int b = 0; b < 8; ++b) { acc0[b] = 0ull; acc1[b] = 0ull; }

        asm volatile("cp.async.wait_group 1;\n" ::: "memory");
        __syncthreads();
        #pragma unroll
        for (int b = 0; b < 4; ++b) {
            const float* hb = hs + b * Hh + kbase;
            #pragma unroll
            for (int i = 0; i < 32; ++i) {
                F4U hv; hv.f = *(const float4*)&hb[i * 4];   // warp-broadcast
                acc0[b] = ffma2_(hv.u[0], wreg[2 * i],     acc0[b]);
                acc1[b] = ffma2_(hv.u[1], wreg[2 * i + 1], acc1[b]);
            }
        }
        asm volatile("cp.async.wait_group 0;\n" ::: "memory");
        __syncthreads();
        #pragma unroll
        for (int b = 4; b < 8; ++b) {
            const float* hb = hs + b * Hh + kbase;
            #pragma unroll
            for (int i = 0; i < 32; ++i) {
                F4U hv; hv.f = *(const float4*)&hb[i * 4];
                acc0[b] = ffma2_(hv.u[0], wreg[2 * i],     acc0[b]);
                acc1[b] = ffma2_(hv.u[1], wreg[2 * i + 1], acc1[b]);
            }
        }

        // k-slice partials -> SMEM
        #pragma unroll
        for (int b = 0; b < 8; ++b) {
            U2F a, c; a.u = acc0[b]; c.u = acc1[b];
            part[w * 256 + b * 32 + jl] = (a.f.x + a.f.y) + (c.f.x + c.f.y);
        }
        __syncthreads();

        // Reduce 8 slices; thread (eb, ej)
        float s = accx;
        #pragma unroll
        for (int ww = 0; ww < 8; ++ww) s += part[ww * 256 + eb * 32 + ej];
        float hn = tanhf(s);
        __stcg(&g_h[(size_t)(t + 1) * BH + (size_t)(bbase + eb) * Hh + jbase + ej], hn);

        if (t == Tt - 1) {
            hf_out[(bbase + eb) * Hh + jbase + ej] = hn;
            break;
        }

        // Per-group barrier (32 CTAs): release -> arrive -> spin -> acquire
        __threadfence();
        __syncthreads();
        if (tid == 0) {
            atomicAdd(bar, 1u);
            unsigned tgt = (unsigned)(t + 1) * 32;
            while (*((volatile unsigned*)bar) < tgt) { }
            __threadfence();
        }
        __syncthreads();
    }
}

// ---------------------------------------------------------------------------
// Backward scan (elementwise, parallel over (b,j)):
//   a_t = c_t + diag(W_hh)[j] * (1 - h_all[t+1]^2) * a_{t+1}, in place in g_c
// ---------------------------------------------------------------------------
__global__ void scan_bwd(const float* __restrict__ Whh)
{
    int flat = blockIdx.x * blockDim.x + threadIdx.x;  // 0..BH-1
    int j = flat & (Hh - 1);
    float dw = Whh[(size_t)j * Hh + j];
    float a = g_c[(size_t)(Tt - 1) * BH + flat];
    for (int t = Tt - 2; t >= 0; --t) {
        float h   = g_h[(size_t)(t + 1) * BH + flat];
        float php = 1.f - h * h;
        a = g_c[(size_t)t * BH + flat] + dw * php * a;
        g_c[(size_t)t * BH + flat] = a;
    }
}

// ---------------------------------------------------------------------------
// Tiled fp32 GEMM, double-buffered, fp32x2 inner with PRE-DUPLICATED B:
// Bs stores every b value as an adjacent (b,b) pair, so the inner loop is
// pure {4x LDS.128 + 16x FFMA2} per kk -- no MOV broadcasts on the issue path.
// Tile TM x 64 (TM = 64 or 128), 256 threads, (TM/16) x 4 micro-tile.
// SPLITK via blockIdx.z (chunk length Kc) + ATOMIC epilogue into zeroed out.
// EPI: 0 plain store; 1 store + err=acc-Q0 into P1; 2 store acc*(1-Q0^2).
// ---------------------------------------------------------------------------
template<int TM, bool AKC, bool BKC, int EPI, bool ATOMIC>
__global__ void __launch_bounds__(256) gemmT(const float* __restrict__ A, int sAm, int sAk,
                                             const float* __restrict__ B, int sBn, int sBk,
                                             int N, int Kc, float scale,
                                             float* __restrict__ P0, float* __restrict__ P1,
                                             const float* __restrict__ Q0)
{
    constexpr int MI  = TM / 16;     // per-thread m extent (4 or 8)
    constexpr int NLA = TM / 64;     // A-loader iterations (1 or 2)
    __shared__ float As[2][16][TM + 4];
    __shared__ float Bs[2][16][136];     // 64 n-values duplicated: [2n],[2n+1]
    int tid = threadIdx.x;
    int m0 = blockIdx.y * TM, n0 = blockIdx.x * 64;
    int kbeg = blockIdx.z * Kc, kend = kbeg + Kc;
    int ty = tid >> 4, tx = tid & 15;

    float4 aP[NLA], bP;
    auto loadA = [&](int k0) {
        #pragma unroll
        for (int it = 0; it < NLA; ++it) {
            int f = tid + (it << 8);
            if (AKC) { int r = f >> 2, kk = (f & 3) << 2;
                aP[it] = *(const float4*)&A[(size_t)(m0 + r) * sAm + k0 + kk]; }
            else { int kk = f / (TM / 4), r = (f % (TM / 4)) << 2;
                aP[it] = *(const float4*)&A[(size_t)(k0 + kk) * sAk + m0 + r]; }
        }
    };
    auto storeA = [&](int p) {
        #pragma unroll
        for (int it = 0; it < NLA; ++it) {
            int f = tid + (it << 8);
            if (AKC) { int r = f >> 2, kk = (f & 3) << 2;
                As[p][kk][r] = aP[it].x; As[p][kk+1][r] = aP[it].y;
                As[p][kk+2][r] = aP[it].z; As[p][kk+3][r] = aP[it].w; }
            else { int kk = f / (TM / 4), r = (f % (TM / 4)) << 2;
                *(float4*)&As[p][kk][r] = aP[it]; }
        }
    };
    auto loadB = [&](int k0) {
        if (BKC) { int r = tid >> 2, kk = (tid & 3) << 2;
            bP = *(const float4*)&B[(size_t)(n0 + r) * sBn + k0 + kk]; }
        else { int kk = tid >> 4, r = (tid & 15) << 2;
            bP = *(const float4*)&B[(size_t)(k0 + kk) * sBk + n0 + r]; }
    };
    auto storeB = [&](int p) {
        if (BKC) {
            // thread holds b[n=r][kk..kk+4) -> write (v,v) pair per kk row
            int r = tid >> 2, kk = (tid & 3) << 2;
            float2 d0 = make_float2(bP.x, bP.x);
            float2 d1 = make_float2(bP.y, bP.y);
            float2 d2 = make_float2(bP.z, bP.z);
            float2 d3 = make_float2(bP.w, bP.w);
            *(float2*)&Bs[p][kk + 0][2 * r] = d0;
            *(float2*)&Bs[p][kk + 1][2 * r] = d1;
            *(float2*)&Bs[p][kk + 2][2 * r] = d2;
            *(float2*)&Bs[p][kk + 3][2 * r] = d3;
        } else {
            // thread holds b[kk][r..r+4) -> contiguous dup run [2r..2r+8)
            int kk = tid >> 4, r = (tid & 15) << 2;
            float4 lo = make_float4(bP.x, bP.x, bP.y, bP.y);
            float4 hi = make_float4(bP.z, bP.z, bP.w, bP.w);
            *(float4*)&Bs[p][kk][2 * r]     = lo;
            *(float4*)&Bs[p][kk][2 * r + 4] = hi;
        }
    };

    loadA(kbeg); loadB(kbeg);
    storeA(0);   storeB(0);
    __syncthreads();

    unsigned long long acc2[MI / 2][4];
    #pragma unroll
    for (int i = 0; i < MI / 2; ++i)
        #pragma unroll
        for (int j = 0; j < 4; ++j) acc2[i][j] = 0ull;

    int p = 0;
    for (int k0 = kbeg; k0 < kend; k0 += 16) {
        bool more = (k0 + 16) < kend;
        if (more) { loadA(k0 + 16); loadB(k0 + 16); }
        #pragma unroll
        for (int kk = 0; kk < 16; ++kk) {
            F4U b01, b23;                       // (n0,n0,n1,n1), (n2,n2,n3,n3)
            b01.f = *(float4*)&Bs[p][kk][8 * tx];
            b23.f = *(float4*)&Bs[p][kk][8 * tx + 4];
            #pragma unroll
            for (int q = 0; q < MI / 4; ++q) {
                F4U av; av.f = *(float4*)&As[p][kk][ty * MI + q * 4];
                acc2[2*q  ][0] = ffma2_(av.u[0], b01.u[0], acc2[2*q  ][0]);
                acc2[2*q+1][0] = ffma2_(av.u[1], b01.u[0], acc2[2*q+1][0]);
                acc2[2*q  ][1] = ffma2_(av.u[0], b01.u[1], acc2[2*q  ][1]);
                acc2[2*q+1][1] = ffma2_(av.u[1], b01.u[1], acc2[2*q+1][1]);
                acc2[2*q  ][2] = ffma2_(av.u[0], b23.u[0], acc2[2*q  ][2]);
                acc2[2*q+1][2] = ffma2_(av.u[1], b23.u[0], acc2[2*q+1][2]);
                acc2[2*q  ][3] = ffma2_(av.u[0], b23.u[1], acc2[2*q  ][3]);
                acc2[2*q+1][3] = ffma2_(av.u[1], b23.u[1], acc2[2*q+1][3]);
            }
        }
        if (more) { storeA(p ^ 1); storeB(p ^ 1); __syncthreads(); p ^= 1; }
    }

    // acc2[pr] holds m-offsets (2pr, 2pr+1) relative to ty*MI (pairs from the
    // float4 halves); epilogue enumerates m = m0 + ty*MI + pr*2 + h2.
    #pragma unroll
    for (int pr = 0; pr < MI / 2; ++pr) {
        #pragma unroll
        for (int h2 = 0; h2 < 2; ++h2) {
            int m = m0 + ty * MI + pr * 2 + h2;
            #pragma unroll
            for (int jx = 0; jx < 4; ++jx) {
                int n = n0 + (tx << 2) + jx;
                U2F uv; uv.u = acc2[pr][jx];
                float v = (h2 ? uv.f.y : uv.f.x) * scale;
                size_t idx = (size_t)m * N + n;
                if (ATOMIC) {
                    atomicAdd(&P0[idx], v);
                } else if (EPI == 0) {
                    P0[idx] = v;
                } else if (EPI == 1) {          // O -> ys, err = O - target
                    P0[idx] = v;
                    P1[idx] = v - Q0[idx];
                } else {                        // c = L * (1 - hnew^2)
                    float h = Q0[idx];
                    P0[idx] = v * (1.f - h * h);
                }
            }
        }
    }
}

// ---------------------------------------------------------------------------
// Launch sequence (graph-capturable: kernel launches only)
// ---------------------------------------------------------------------------
extern "C" void kernel_launch(void* const* d_in, const int* in_sizes, int n_in,
                              void* d_out, int out_size)
{
    const float* x      = (const float*)d_in[0];  // [T,B,I]
    const float* target = (const float*)d_in[1];  // [T,B,O]
    const float* h0     = (const float*)d_in[2];  // [B,H]
    const float* W_in   = (const float*)d_in[3];  // [H,I]
    const float* W_hh   = (const float*)d_in[4];  // [H,H]
    const float* W_out  = (const float*)d_in[5];  // [O,H]

    float* out   = (float*)d_out;
    float* ys    = out;                                   // [T*B, O]
    float* hf    = out + (size_t)MROWS * Oo;              // [B,H]
    float* gwout = hf + BH;                               // [O,H]
    float* gwih  = gwout + (size_t)Oo * Hh;               // [H,I]
    float* gwhh  = gwih + (size_t)Hh * Ii;                // [H,H]

    float *p_xin, *p_h, *p_err, *p_c;
    cudaGetSymbolAddress((void**)&p_xin, g_xin);
    cudaGetSymbolAddress((void**)&p_h,   g_h);
    cudaGetSymbolAddress((void**)&p_err, g_err);
    cudaGetSymbolAddress((void**)&p_c,   g_c);

    // 0. zero split-K accumulation targets (gwout..gwhh contiguous) + barriers
    // (kNumZero, NOT "NZERO": glibc <limits.h> defines NZERO=20 on the GPU host)
    const int kNumZero = Oo * Hh + Hh * Ii + Hh * Hh;   // 1,441,792 floats
    zero_kernel<<<256, 256>>>(gwout, kNumZero);

    // 1. Xin = X @ W_in^T            [4096,1024], K=256  (DOT)
    gemmT<128, true, true, 0, false><<<dim3(Hh / 64, MROWS / 128, 1), 256>>>(
        x, Ii, 1, W_in, Ii, 1, Hh, Ii, 1.f, p_xin, nullptr, nullptr);

    // 2. init h_all[0]
    init_kernel<<<BH / 256, 256>>>(h0);

    // 3. forward scan (persistent, 4 batch-groups x 32 slices, 256 thr)
    scan_fwd<<<128, 256>>>(W_hh, hf);

    // 4. O = Hnew @ W_out^T -> ys; err = O - target      [4096,128], K=1024 (DOT)
    gemmT<64, true, true, 1, false><<<dim3(Oo / 64, MROWS / 64, 1), 256>>>(
        p_h + BH, Hh, 1, W_out, Hh, 1, Oo, Hh, 1.f, ys, p_err, target);

    // 5. c = (err @ W_out) * (1 - hnew^2)                [4096,1024], K=128 (NN)
    gemmT<128, true, false, 2, false><<<dim3(Hh / 64, MROWS / 128, 1), 256>>>(
        p_err, Oo, 1, W_out, 1, Hh, Hh, Oo, 1.f, p_c, nullptr, p_h + BH);

    // 6. backward scan: c -> a (in place)
    scan_bwd<<<BH / 256, 256>>>(W_hh);

    // 7. g_wout = (1/B) * err^T @ Hnew       [128,1024], K=4096, split 8 -> 128 CTAs
    gemmT<128, false, false, 0, true><<<dim3(Hh / 64, Oo / 128, 8), 256>>>(
        p_err, 1, Oo, p_h + BH, 1, Hh, Hh, MROWS / 8, 1.f / Bb, gwout, nullptr, nullptr);

    // 8. g_wih = (1e-3/B) * a^T @ X          [1024,256], K=4096, split 4 -> 128 CTAs
    gemmT<128, false, false, 0, true><<<dim3(Ii / 64, Hh / 128, 4), 256>>>(
        p_c, 1, Hh, x, 1, Ii, Ii, MROWS / 4, 1e-3f / Bb, gwih, nullptr, nullptr);

    // 9. g_whh = (1e-5/B) * a^T @ Hprev      [1024,1024], K=4096, split 2 -> 256 CTAs
    gemmT<128, false, false, 0, true><<<dim3(Hh / 64, Hh / 128, 2), 256>>>(
        p_c, 1, Hh, p_h, 1, Hh, Hh, MROWS / 2, 1e-5f / Bb, gwhh, nullptr, nullptr);
}

// round 14
// speedup vs baseline: 1.4212x; 1.4212x over previous
#include <cuda_runtime.h>
#include <cuda_bf16.h>
#include <cstdint>

// Problem dims
#define Tt 128
#define Bb 32
#define Ii 256
#define Hh 1024
#define Oo 128
#define BH (Bb*Hh)      // 32768 floats per timestep of h
#define MROWS (Tt*Bb)   // 4096 flattened (t,b) rows

// Scratch (device globals: no allocations allowed)
__device__ float g_xin[Tt*BH];        // X @ W_in^T, [T,B,H]
__device__ float g_h[(Tt+1)*BH];      // h_all[0..T], [T+1,B,H]
__device__ float g_err[MROWS*Oo];     // err, [T*B,O]
__device__ float g_c[MROWS*Hh];       // c, then (in-place) a, [T*B,H]
__device__ unsigned g_bars[128];      // 4 group barriers, stride 32 (separate lines)

// ---------------------------------------------------------------------------
// Packed fp32x2 FMA (Blackwell FFMA2: 2 fp32 FMAs per instruction)
// ---------------------------------------------------------------------------
__device__ __forceinline__ unsigned long long ffma2_(unsigned long long a,
                                                     unsigned long long b,
                                                     unsigned long long c)
{
    unsigned long long d;
    asm("fma.rn.f32x2 %0, %1, %2, %3;" : "=l"(d) : "l"(a), "l"(b), "l"(c));
    return d;
}
__device__ __forceinline__ unsigned long long dup2_(float x)
{
    unsigned long long d;
    asm("mov.b64 %0, {%1, %1};" : "=l"(d) : "f"(x));
    return d;
}
union F4U { float4 f; unsigned long long u[2]; float s[4]; };
union U2F { unsigned long long u; float2 f; };

// ---------------------------------------------------------------------------
// cp.async helper (LDGSTS .cg: bypasses L1 -> coherent with other SMs' stores)
// ---------------------------------------------------------------------------
__device__ __forceinline__ void cp16(uint32_t saddr, const void* gptr)
{
    asm volatile("cp.async.cg.shared.global [%0], [%1], 16;\n" :: "r"(saddr), "l"(gptr));
}

// ---------------------------------------------------------------------------
// setup_kernel: zero split-K targets + reset barriers + copy h0 into g_h[0]
// ---------------------------------------------------------------------------
__global__ void setup_kernel(float* __restrict__ p, int n, const float* __restrict__ h0)
{
    int i = blockIdx.x * blockDim.x + threadIdx.x;
    if (i < 128) g_bars[i] = 0u;
    if (i < BH) g_h[i] = h0[i];
    for (; i < n; i += gridDim.x * blockDim.x) p[i] = 0.f;
}

// ---------------------------------------------------------------------------
// Forward scan: h_{t+1} = tanh(xin_t + h_t @ W_hh^T)
// (R9 configuration — best measured: 545us. 4 groups x 32 slices, 256 thr.)
// group g owns batches [8g,8g+8); CTA slice s owns rows [32s,32s+32).
// W_hh in registers: warp w (0..7) = k-slice [128w,128w+128); lane jl = row.
// R14 tweak: barrier uses atom.add.release.gpu + ld.acquire.gpu spin —
// drops both __threadfence() calls (store -> bar.sync -> release-flag is the
// canonical publish pattern; ordering preserved by scoped acq/rel).
// ---------------------------------------------------------------------------
__global__ void __launch_bounds__(256, 1) scan_fwd(const float* __restrict__ Whh,
                                                   float* __restrict__ hf_out)
{
    __shared__ float hs[8 * Hh];          // 32KB staged h for this group's batches
    __shared__ float part[8 * 8 * 32];    // 8KB partials [kslice][b][j]

    int tid = threadIdx.x;
    int grp = blockIdx.x >> 5;            // batch group 0..3
    int sl  = blockIdx.x & 31;            // row slice 0..31
    int jbase = sl * 32;
    int bbase = grp * 8;

    int w  = tid >> 5;                    // k-slice == warp id (0..7)
    int jl = tid & 31;                    // row within slice (lane)
    int kbase = w * 128;

    // One-time: W[jbase+jl][kbase .. kbase+128) into 64 f32x2 registers
    unsigned long long wreg[64];
    {
        const float* wr = Whh + (size_t)(jbase + jl) * Hh + kbase;
        #pragma unroll
        for (int i = 0; i < 32; ++i) {
            F4U v; v.f = *(const float4*)&wr[i * 4];
            wreg[2 * i] = v.u[0]; wreg[2 * i + 1] = v.u[1];
        }
    }

    int eb = tid >> 5;                    // epilogue batch (0..7)
    int ej = tid & 31;                    // epilogue row within slice
    uint32_t hs_base = (uint32_t)__cvta_generic_to_shared(hs);
    unsigned* bar = &g_bars[grp * 32];

    for (int t = 0; t < Tt; ++t) {
        const float* hcur = g_h + (size_t)t * BH + (size_t)bbase * Hh;

        // Stage 8*1024 floats = 2048 float4 over 256 threads; 2 commit groups
        #pragma unroll
        for (int r = 0; r < 4; ++r) {
            int f = tid + (r << 8);
            cp16(hs_base + (f << 4), hcur + (f << 2));
        }
        asm volatile("cp.async.commit_group;\n");
        #pragma unroll
        for (int r = 4; r < 8; ++r) {
            int f = tid + (r << 8);
            cp16(hs_base + (f << 4), hcur + (f << 2));
        }
        asm volatile("cp.async.commit_group;\n");

        float accx = g_xin[(size_t)t * BH + (size_t)(bbase + eb) * Hh + jbase + ej];

        unsigned long long acc0[8], acc1[8];   // 2 chains per batch
        #pragma unroll
        for (int b = 0; b < 8; ++b) { acc0[b] = 0ull; acc1[b] = 0ull; }

        asm volatile("cp.async.wait_group 1;\n" ::: "memory");
        __syncthreads();
        #pragma unroll
        for (int b = 0; b < 4; ++b) {
            const float* hb = hs + b * Hh + kbase;
            #pragma unroll
            for (int i = 0; i < 32; ++i) {
                F4U hv; hv.f = *(const float4*)&hb[i * 4];   // warp-broadcast
                acc0[b] = ffma2_(hv.u[0], wreg[2 * i],     acc0[b]);
                acc1[b] = ffma2_(hv.u[1], wreg[2 * i + 1], acc1[b]);
            }
        }
        asm volatile("cp.async.wait_group 0;\n" ::: "memory");
        __syncthreads();
        #pragma unroll
        for (int b = 4; b < 8; ++b) {
            const float* hb = hs + b * Hh + kbase;
            #pragma unroll
            for (int i = 0; i < 32; ++i) {
                F4U hv; hv.f = *(const float4*)&hb[i * 4];
                acc0[b] = ffma2_(hv.u[0], wreg[2 * i],     acc0[b]);
                acc1[b] = ffma2_(hv.u[1], wreg[2 * i + 1], acc1[b]);
            }
        }

        // k-slice partials -> SMEM
        #pragma unroll
        for (int b = 0; b < 8; ++b) {
            U2F a, c; a.u = acc0[b]; c.u = acc1[b];
            part[w * 256 + b * 32 + jl] = (a.f.x + a.f.y) + (c.f.x + c.f.y);
        }
        __syncthreads();

        // Reduce 8 slices; thread (eb, ej)
        float s = accx;
        #pragma unroll
        for (int ww = 0; ww < 8; ++ww) s += part[ww * 256 + eb * 32 + ej];
        float hn = tanhf(s);
        __stcg(&g_h[(size_t)(t + 1) * BH + (size_t)(bbase + eb) * Hh + jbase + ej], hn);

        if (t == Tt - 1) {
            hf_out[(bbase + eb) * Hh + jbase + ej] = hn;
            break;
        }

        // Per-group barrier (32 CTAs): stores -> bar.sync -> release-add,
        // acquire-spin. No threadfence needed.
        __syncthreads();
        if (tid == 0) {
            unsigned prev;
            asm volatile("atom.add.release.gpu.u32 %0, [%1], %2;"
                         : "=r"(prev) : "l"(bar), "r"(1u) : "memory");
            unsigned tgt = (unsigned)(t + 1) * 32;
            unsigned v;
            do {
                asm volatile("ld.acquire.gpu.u32 %0, [%1];"
                             : "=r"(v) : "l"(bar) : "memory");
            } while (v < tgt);
        }
        __syncthreads();
    }
}

// ---------------------------------------------------------------------------
// Backward scan (elementwise, parallel over (b,j)):
//   a_t = c_t + diag(W_hh)[j] * (1 - h_all[t+1]^2) * a_{t+1}, in place in g_c
// ---------------------------------------------------------------------------
__global__ void scan_bwd(const float* __restrict__ Whh)
{
    int flat = blockIdx.x * blockDim.x + threadIdx.x;  // 0..BH-1
    int j = flat & (Hh - 1);
    float dw = Whh[(size_t)j * Hh + j];
    float a = g_c[(size_t)(Tt - 1) * BH + flat];
    for (int t = Tt - 2; t >= 0; --t) {
        float h   = g_h[(size_t)(t + 1) * BH + flat];
        float php = 1.f - h * h;
        a = g_c[(size_t)t * BH + flat] + dw * php * a;
        g_c[(size_t)t * BH + flat] = a;
    }
}

// ---------------------------------------------------------------------------
// Tiled fp32 GEMM, double-buffered, fp32x2 inner (R11 version — measured
// good; dup MOVs hide under the 32-cycle FFMA2 floor, Bs rows 68 floats are
// conflict-free). Tile TM x 64, 256 threads, (TM/16) x 4 micro-tile.
// SPLITK via blockIdx.z (chunk length Kc) + ATOMIC epilogue into zeroed out.
// EPI: 0 plain store; 1 store + err=acc-Q0 into P1; 2 store acc*(1-Q0^2).
// ---------------------------------------------------------------------------
template<int TM, bool AKC, bool BKC, int EPI, bool ATOMIC>
__global__ void __launch_bounds__(256) gemmT(const float* __restrict__ A, int sAm, int sAk,
                                             const float* __restrict__ B, int sBn, int sBk,
                                             int N, int Kc, float scale,
                                             float* __restrict__ P0, float* __restrict__ P1,
                                             const float* __restrict__ Q0)
{
    constexpr int MI  = TM / 16;     // per-thread m extent (4 or 8)
    constexpr int NLA = TM / 64;     // A-loader iterations (1 or 2)
    __shared__ float As[2][16][TM + 4];
    __shared__ float Bs[2][16][68];
    int tid = threadIdx.x;
    int m0 = blockIdx.y * TM, n0 = blockIdx.x * 64;
    int kbeg = blockIdx.z * Kc, kend = kbeg + Kc;
    int ty = tid >> 4, tx = tid & 15;

    float4 aP[NLA], bP;
    auto loadA = [&](int k0) {
        #pragma unroll
        for (int it = 0; it < NLA; ++it) {
            int f = tid + (it << 8);
            if (AKC) { int r = f >> 2, kk = (f & 3) << 2;
                aP[it] = *(const float4*)&A[(size_t)(m0 + r) * sAm + k0 + kk]; }
            else { int kk = f / (TM / 4), r = (f % (TM / 4)) << 2;
                aP[it] = *(const float4*)&A[(size_t)(k0 + kk) * sAk + m0 + r]; }
        }
    };
    auto storeA = [&](int p) {
        #pragma unroll
        for (int it = 0; it < NLA; ++it) {
            int f = tid + (it << 8);
            if (AKC) { int r = f >> 2, kk = (f & 3) << 2;
                As[p][kk][r] = aP[it].x; As[p][kk+1][r] = aP[it].y;
                As[p][kk+2][r] = aP[it].z; As[p][kk+3][r] = aP[it].w; }
            else { int kk = f / (TM / 4), r = (f % (TM / 4)) << 2;
                *(float4*)&As[p][kk][r] = aP[it]; }
        }
    };
    auto loadB = [&](int k0) {
        if (BKC) { int r = tid >> 2, kk = (tid & 3) << 2;
            bP = *(const float4*)&B[(size_t)(n0 + r) * sBn + k0 + kk]; }
        else { int kk = tid >> 4, r = (tid & 15) << 2;
            bP = *(const float4*)&B[(size_t)(k0 + kk) * sBk + n0 + r]; }
    };
    auto storeB = [&](int p) {
        if (BKC) { int r = tid >> 2, kk = (tid & 3) << 2;
            Bs[p][kk][r] = bP.x; Bs[p][kk+1][r] = bP.y;
            Bs[p][kk+2][r] = bP.z; Bs[p][kk+3][r] = bP.w; }
        else { int kk = tid >> 4, r = (tid & 15) << 2;
            *(float4*)&Bs[p][kk][r] = bP; }
    };

    loadA(kbeg); loadB(kbeg);
    storeA(0);   storeB(0);
    __syncthreads();

    unsigned long long acc2[MI / 2][4];
    #pragma unroll
    for (int i = 0; i < MI / 2; ++i)
        #pragma unroll
        for (int j = 0; j < 4; ++j) acc2[i][j] = 0ull;

    int p = 0;
    for (int k0 = kbeg; k0 < kend; k0 += 16) {
        bool more = (k0 + 16) < kend;
        if (more) { loadA(k0 + 16); loadB(k0 + 16); }
        #pragma unroll
        for (int kk = 0; kk < 16; ++kk) {
            F4U bv; bv.f = *(float4*)&Bs[p][kk][tx << 2];
            unsigned long long d0 = dup2_(bv.s[0]), d1 = dup2_(bv.s[1]);
            unsigned long long d2 = dup2_(bv.s[2]), d3 = dup2_(bv.s[3]);
            #pragma unroll
            for (int q = 0; q < MI / 4; ++q) {
                F4U av; av.f = *(float4*)&As[p][kk][ty * MI + q * 4];
                acc2[2*q  ][0] = ffma2_(av.u[0], d0, acc2[2*q  ][0]);
                acc2[2*q+1][0] = ffma2_(av.u[1], d0, acc2[2*q+1][0]);
                acc2[2*q  ][1] = ffma2_(av.u[0], d1, acc2[2*q  ][1]);
                acc2[2*q+1][1] = ffma2_(av.u[1], d1, acc2[2*q+1][1]);
                acc2[2*q  ][2] = ffma2_(av.u[0], d2, acc2[2*q  ][2]);
                acc2[2*q+1][2] = ffma2_(av.u[1], d2, acc2[2*q+1][2]);
                acc2[2*q  ][3] = ffma2_(av.u[0], d3, acc2[2*q  ][3]);
                acc2[2*q+1][3] = ffma2_(av.u[1], d3, acc2[2*q+1][3]);
            }
        }
        if (more) { storeA(p ^ 1); storeB(p ^ 1); __syncthreads(); p ^= 1; }
    }

    // acc2[pr] holds m-offsets (2pr, 2pr+1) relative to ty*MI (pairs from the
    // float4 halves); epilogue enumerates m = m0 + ty*MI + pr*2 + h2.
    #pragma unroll
    for (int pr = 0; pr < MI / 2; ++pr) {
        #pragma unroll
        for (int h2 = 0; h2 < 2; ++h2) {
            int m = m0 + ty * MI + pr * 2 + h2;
            #pragma unroll
            for (int jx = 0; jx < 4; ++jx) {
                int n = n0 + (tx << 2) + jx;
                U2F uv; uv.u = acc2[pr][jx];
                float v = (h2 ? uv.f.y : uv.f.x) * scale;
                size_t idx = (size_t)m * N + n;
                if (ATOMIC) {
                    atomicAdd(&P0[idx], v);
                } else if (EPI == 0) {
                    P0[idx] = v;
                } else if (EPI == 1) {          // O -> ys, err = O - target
                    P0[idx] = v;
                    P1[idx] = v - Q0[idx];
                } else {                        // c = L * (1 - hnew^2)
                    float h = Q0[idx];
                    P0[idx] = v * (1.f - h * h);
                }
            }
        }
    }
}

// ---------------------------------------------------------------------------
// Launch sequence (graph-capturable: kernel launches only)
// ---------------------------------------------------------------------------
extern "C" void kernel_launch(void* const* d_in, const int* in_sizes, int n_in,
                              void* d_out, int out_size)
{
    const float* x      = (const float*)d_in[0];  // [T,B,I]
    const float* target = (const float*)d_in[1];  // [T,B,O]
    const float* h0     = (const float*)d_in[2];  // [B,H]
    const float* W_in   = (const float*)d_in[3];  // [H,I]
    const float* W_hh   = (const float*)d_in[4];  // [H,H]
    const float* W_out  = (const float*)d_in[5];  // [O,H]

    float* out   = (float*)d_out;
    float* ys    = out;                                   // [T*B, O]
    float* hf    = out + (size_t)MROWS * Oo;              // [B,H]
    float* gwout = hf + BH;                               // [O,H]
    float* gwih  = gwout + (size_t)Oo * Hh;               // [H,I]
    float* gwhh  = gwih + (size_t)Hh * Ii;                // [H,H]

    float *p_xin, *p_h, *p_err, *p_c;
    cudaGetSymbolAddress((void**)&p_xin, g_xin);
    cudaGetSymbolAddress((void**)&p_h,   g_h);
    cudaGetSymbolAddress((void**)&p_err, g_err);
    cudaGetSymbolAddress((void**)&p_c,   g_c);

    // 0. zero split-K accumulation targets + barriers + h_all[0] (one kernel)
    // (kNumZero, NOT "NZERO": glibc <limits.h> defines NZERO=20 on the GPU host)
    const int kNumZero = Oo * Hh + Hh * Ii + Hh * Hh;   // 1,441,792 floats
    setup_kernel<<<256, 256>>>(gwout, kNumZero, h0);

    // 1. Xin = X @ W_in^T            [4096,1024], K=256  (DOT)
    gemmT<128, true, true, 0, false><<<dim3(Hh / 64, MROWS / 128, 1), 256>>>(
        x, Ii, 1, W_in, Ii, 1, Hh, Ii, 1.f, p_xin, nullptr, nullptr);

    // 2. forward scan (persistent, 4 batch-groups x 32 slices, 256 thr)
    scan_fwd<<<128, 256>>>(W_hh, hf);

    // 3. O = Hnew @ W_out^T -> ys; err = O - target      [4096,128], K=1024 (DOT)
    gemmT<64, true, true, 1, false><<<dim3(Oo / 64, MROWS / 64, 1), 256>>>(
        p_h + BH, Hh, 1, W_out, Hh, 1, Oo, Hh, 1.f, ys, p_err, target);

    // 4. c = (err @ W_out) * (1 - hnew^2)                [4096,1024], K=128 (NN)
    gemmT<128, true, false, 2, false><<<dim3(Hh / 64, MROWS / 128, 1), 256>>>(
        p_err, Oo, 1, W_out, 1, Hh, Hh, Oo, 1.f, p_c, nullptr, p_h + BH);

    // 5. backward scan: c -> a (in place)
    scan_bwd<<<BH / 256, 256>>>(W_hh);

    // 6. g_wout = (1/B) * err^T @ Hnew       [128,1024], K=4096, split 8 -> 128 CTAs
    gemmT<128, false, false, 0, true><<<dim3(Hh / 64, Oo / 128, 8), 256>>>(
        p_err, 1, Oo, p_h + BH, 1, Hh, Hh, MROWS / 8, 1.f / Bb, gwout, nullptr, nullptr);

    // 7. g_wih = (1e-3/B) * a^T @ X          [1024,256], K=4096, split 4 -> 128 CTAs
    gemmT<128, false, false, 0, true><<<dim3(Ii / 64, Hh / 128, 4), 256>>>(
        p_c, 1, Hh, x, 1, Ii, Ii, MROWS / 4, 1e-3f / Bb, gwih, nullptr, nullptr);

    // 8. g_whh = (1e-5/B) * a^T @ Hprev      [1024,1024], K=4096, split 2 -> 256 CTAs
    gemmT<128, false, false, 0, true><<<dim3(Hh / 64, Hh / 128, 2), 256>>>(
        p_c, 1, Hh, p_h, 1, Hh, Hh, MROWS / 2, 1e-5f / Bb, gwhh, nullptr, nullptr);
}

// round 15
// speedup vs baseline: 1.4337x; 1.0087x over previous
#include <cuda_runtime.h>
#include <cuda_bf16.h>
#include <cstdint>

// Problem dims
#define Tt 128
#define Bb 32
#define Ii 256
#define Hh 1024
#define Oo 128
#define BH (Bb*Hh)      // 32768 floats per timestep of h
#define MROWS (Tt*Bb)   // 4096 flattened (t,b) rows

// Scratch (device globals: no allocations allowed)
__device__ float g_xin[Tt*BH];        // X @ W_in^T, [T,B,H]
__device__ float g_h[(Tt+1)*BH];      // h_all[0..T], [T+1,B,H]
__device__ float g_err[MROWS*Oo];     // err, [T*B,O]
__device__ float g_c[MROWS*Hh];       // c, then (in-place) a, [T*B,H]
__device__ unsigned g_bars[128];      // 4 group barriers, stride 32 (separate lines)

// ---------------------------------------------------------------------------
// Packed fp32x2 FMA (Blackwell FFMA2: 2 fp32 FMAs per instruction)
// ---------------------------------------------------------------------------
__device__ __forceinline__ unsigned long long ffma2_(unsigned long long a,
                                                     unsigned long long b,
                                                     unsigned long long c)
{
    unsigned long long d;
    asm("fma.rn.f32x2 %0, %1, %2, %3;" : "=l"(d) : "l"(a), "l"(b), "l"(c));
    return d;
}
__device__ __forceinline__ unsigned long long dup2_(float x)
{
    unsigned long long d;
    asm("mov.b64 %0, {%1, %1};" : "=l"(d) : "f"(x));
    return d;
}
union F4U { float4 f; unsigned long long u[2]; float s[4]; };
union U2F { unsigned long long u; float2 f; };

// ---------------------------------------------------------------------------
// cp.async helper (LDGSTS .cg: bypasses L1 -> coherent with other SMs' stores)
// ---------------------------------------------------------------------------
__device__ __forceinline__ void cp16(uint32_t saddr, const void* gptr)
{
    asm volatile("cp.async.cg.shared.global [%0], [%1], 16;\n" :: "r"(saddr), "l"(gptr));
}

// ---------------------------------------------------------------------------
// setup_kernel: zero ys + split-K targets, reset barriers, copy h0 -> g_h[0]
// err_kernel:  err = ys - target (elementwise, after split-K O GEMM)
// ---------------------------------------------------------------------------
__global__ void setup_kernel(float* __restrict__ ys, int nys,
                             float* __restrict__ gw, int ngw,
                             const float* __restrict__ h0)
{
    int i = blockIdx.x * blockDim.x + threadIdx.x;
    if (i < 128) g_bars[i] = 0u;
    if (i < BH) g_h[i] = h0[i];
    for (int k = i; k < nys; k += gridDim.x * blockDim.x) ys[k] = 0.f;
    for (int k = i; k < ngw; k += gridDim.x * blockDim.x) gw[k] = 0.f;
}

__global__ void err_kernel(const float* __restrict__ ys,
                           const float* __restrict__ target)
{
    int i = blockIdx.x * blockDim.x + threadIdx.x;
    if (i < MROWS * Oo) g_err[i] = ys[i] - target[i];
}

// ---------------------------------------------------------------------------
// Forward scan: h_{t+1} = tanh(xin_t + h_t @ W_hh^T)
// (Best-measured configuration; frozen. 4 groups x 32 slices, 256 thr.)
// group g owns batches [8g,8g+8); CTA slice s owns rows [32s,32s+32).
// W_hh in registers: warp w (0..7) = k-slice [128w,128w+128); lane jl = row.
// Barrier: stores -> bar.sync -> atom.add.release.gpu + ld.acquire.gpu spin.
// ---------------------------------------------------------------------------
__global__ void __launch_bounds__(256, 1) scan_fwd(const float* __restrict__ Whh,
                                                   float* __restrict__ hf_out)
{
    __shared__ float hs[8 * Hh];          // 32KB staged h for this group's batches
    __shared__ float part[8 * 8 * 32];    // 8KB partials [kslice][b][j]

    int tid = threadIdx.x;
    int grp = blockIdx.x >> 5;            // batch group 0..3
    int sl  = blockIdx.x & 31;            // row slice 0..31
    int jbase = sl * 32;
    int bbase = grp * 8;

    int w  = tid >> 5;                    // k-slice == warp id (0..7)
    int jl = tid & 31;                    // row within slice (lane)
    int kbase = w * 128;

    // One-time: W[jbase+jl][kbase .. kbase+128) into 64 f32x2 registers
    unsigned long long wreg[64];
    {
        const float* wr = Whh + (size_t)(jbase + jl) * Hh + kbase;
        #pragma unroll
        for (int i = 0; i < 32; ++i) {
            F4U v; v.f = *(const float4*)&wr[i * 4];
            wreg[2 * i] = v.u[0]; wreg[2 * i + 1] = v.u[1];
        }
    }

    int eb = tid >> 5;                    // epilogue batch (0..7)
    int ej = tid & 31;                    // epilogue row within slice
    uint32_t hs_base = (uint32_t)__cvta_generic_to_shared(hs);
    unsigned* bar = &g_bars[grp * 32];

    for (int t = 0; t < Tt; ++t) {
        const float* hcur = g_h + (size_t)t * BH + (size_t)bbase * Hh;

        // Stage 8*1024 floats = 2048 float4 over 256 threads; 2 commit groups
        #pragma unroll
        for (int r = 0; r < 4; ++r) {
            int f = tid + (r << 8);
            cp16(hs_base + (f << 4), hcur + (f << 2));
        }
        asm volatile("cp.async.commit_group;\n");
        #pragma unroll
        for (int r = 4; r < 8; ++r) {
            int f = tid + (r << 8);
            cp16(hs_base + (f << 4), hcur + (f << 2));
        }
        asm volatile("cp.async.commit_group;\n");

        float accx = g_xin[(size_t)t * BH + (size_t)(bbase + eb) * Hh + jbase + ej];

        unsigned long long acc0[8], acc1[8];   // 2 chains per batch
        #pragma unroll
        for (int b = 0; b < 8; ++b) { acc0[b] = 0ull; acc1[b] = 0ull; }

        asm volatile("cp.async.wait_group 1;\n" ::: "memory");
        __syncthreads();
        #pragma unroll
        for (int b = 0; b < 4; ++b) {
            const float* hb = hs + b * Hh + kbase;
            #pragma unroll
            for (int i = 0; i < 32; ++i) {
                F4U hv; hv.f = *(const float4*)&hb[i * 4];   // warp-broadcast
                acc0[b] = ffma2_(hv.u[0], wreg[2 * i],     acc0[b]);
                acc1[b] = ffma2_(hv.u[1], wreg[2 * i + 1], acc1[b]);
            }
        }
        asm volatile("cp.async.wait_group 0;\n" ::: "memory");
        __syncthreads();
        #pragma unroll
        for (int b = 4; b < 8; ++b) {
            const float* hb = hs + b * Hh + kbase;
            #pragma unroll
            for (int i = 0; i < 32; ++i) {
                F4U hv; hv.f = *(const float4*)&hb[i * 4];
                acc0[b] = ffma2_(hv.u[0], wreg[2 * i],     acc0[b]);
                acc1[b] = ffma2_(hv.u[1], wreg[2 * i + 1], acc1[b]);
            }
        }

        // k-slice partials -> SMEM
        #pragma unroll
        for (int b = 0; b < 8; ++b) {
            U2F a, c; a.u = acc0[b]; c.u = acc1[b];
            part[w * 256 + b * 32 + jl] = (a.f.x + a.f.y) + (c.f.x + c.f.y);
        }
        __syncthreads();

        // Reduce 8 slices; thread (eb, ej)
        float s = accx;
        #pragma unroll
        for (int ww = 0; ww < 8; ++ww) s += part[ww * 256 + eb * 32 + ej];
        float hn = tanhf(s);
        __stcg(&g_h[(size_t)(t + 1) * BH + (size_t)(bbase + eb) * Hh + jbase + ej], hn);

        if (t == Tt - 1) {
            hf_out[(bbase + eb) * Hh + jbase + ej] = hn;
            break;
        }

        // Per-group barrier (32 CTAs): stores -> bar.sync -> release-add,
        // acquire-spin. No threadfence needed.
        __syncthreads();
        if (tid == 0) {
            unsigned prev;
            asm volatile("atom.add.release.gpu.u32 %0, [%1], %2;"
                         : "=r"(prev) : "l"(bar), "r"(1u) : "memory");
            unsigned tgt = (unsigned)(t + 1) * 32;
            unsigned v;
            do {
                asm volatile("ld.acquire.gpu.u32 %0, [%1];"
                             : "=r"(v) : "l"(bar) : "memory");
            } while (v < tgt);
        }
        __syncthreads();
    }
}

// ---------------------------------------------------------------------------
// Backward scan (elementwise, parallel over (b,j)):
//   a_t = c_t + diag(W_hh)[j] * (1 - h_all[t+1]^2) * a_{t+1}, in place in g_c
// ---------------------------------------------------------------------------
__global__ void scan_bwd(const float* __restrict__ Whh)
{
    int flat = blockIdx.x * blockDim.x + threadIdx.x;  // 0..BH-1
    int j = flat & (Hh - 1);
    float dw = Whh[(size_t)j * Hh + j];
    float a = g_c[(size_t)(Tt - 1) * BH + flat];
    for (int t = Tt - 2; t >= 0; --t) {
        float h   = g_h[(size_t)(t + 1) * BH + flat];
        float php = 1.f - h * h;
        a = g_c[(size_t)t * BH + flat] + dw * php * a;
        g_c[(size_t)t * BH + flat] = a;
    }
}

// ---------------------------------------------------------------------------
// Tiled fp32 GEMM, double-buffered, fp32x2 inner (best-measured engine;
// dup MOVs hide under the FFMA2 floor, Bs rows 68 floats conflict-free).
// Tile TM x 64, 256 threads, (TM/16) x 4 micro-tile.
// SPLITK via blockIdx.z (chunk length Kc) + ATOMIC epilogue into zeroed out.
// EPI: 0 plain store; 1 store + err=acc-Q0 into P1; 2 store acc*(1-Q0^2).
// ---------------------------------------------------------------------------
template<int TM, bool AKC, bool BKC, int EPI, bool ATOMIC>
__global__ void __launch_bounds__(256) gemmT(const float* __restrict__ A, int sAm, int sAk,
                                             const float* __restrict__ B, int sBn, int sBk,
                                             int N, int Kc, float scale,
                                             float* __restrict__ P0, float* __restrict__ P1,
                                             const float* __restrict__ Q0)
{
    constexpr int MI  = TM / 16;     // per-thread m extent (4 or 8)
    constexpr int NLA = TM / 64;     // A-loader iterations (1 or 2)
    __shared__ float As[2][16][TM + 4];
    __shared__ float Bs[2][16][68];
    int tid = threadIdx.x;
    int m0 = blockIdx.y * TM, n0 = blockIdx.x * 64;
    int kbeg = blockIdx.z * Kc, kend = kbeg + Kc;
    int ty = tid >> 4, tx = tid & 15;

    float4 aP[NLA], bP;
    auto loadA = [&](int k0) {
        #pragma unroll
        for (int it = 0; it < NLA; ++it) {
            int f = tid + (it << 8);
            if (AKC) { int r = f >> 2, kk = (f & 3) << 2;
                aP[it] = *(const float4*)&A[(size_t)(m0 + r) * sAm + k0 + kk]; }
            else { int kk = f / (TM / 4), r = (f % (TM / 4)) << 2;
                aP[it] = *(const float4*)&A[(size_t)(k0 + kk) * sAk + m0 + r]; }
        }
    };
    auto storeA = [&](int p) {
        #pragma unroll
        for (int it = 0; it < NLA; ++it) {
            int f = tid + (it << 8);
            if (AKC) { int r = f >> 2, kk = (f & 3) << 2;
                As[p][kk][r] = aP[it].x; As[p][kk+1][r] = aP[it].y;
                As[p][kk+2][r] = aP[it].z; As[p][kk+3][r] = aP[it].w; }
            else { int kk = f / (TM / 4), r = (f % (TM / 4)) << 2;
                *(float4*)&As[p][kk][r] = aP[it]; }
        }
    };
    auto loadB = [&](int k0) {
        if (BKC) { int r = tid >> 2, kk = (tid & 3) << 2;
            bP = *(const float4*)&B[(size_t)(n0 + r) * sBn + k0 + kk]; }
        else { int kk = tid >> 4, r = (tid & 15) << 2;
            bP = *(const float4*)&B[(size_t)(k0 + kk) * sBk + n0 + r]; }
    };
    auto storeB = [&](int p) {
        if (BKC) { int r = tid >> 2, kk = (tid & 3) << 2;
            Bs[p][kk][r] = bP.x; Bs[p][kk+1][r] = bP.y;
            Bs[p][kk+2][r] = bP.z; Bs[p][kk+3][r] = bP.w; }
        else { int kk = tid >> 4, r = (tid & 15) << 2;
            *(float4*)&Bs[p][kk][r] = bP; }
    };

    loadA(kbeg); loadB(kbeg);
    storeA(0);   storeB(0);
    __syncthreads();

    unsigned long long acc2[MI / 2][4];
    #pragma unroll
    for (int i = 0; i < MI / 2; ++i)
        #pragma unroll
        for (int j = 0; j < 4; ++j) acc2[i][j] = 0ull;

    int p = 0;
    for (int k0 = kbeg; k0 < kend; k0 += 16) {
        bool more = (k0 + 16) < kend;
        if (more) { loadA(k0 + 16); loadB(k0 + 16); }
        #pragma unroll
        for (int kk = 0; kk < 16; ++kk) {
            F4U bv; bv.f = *(float4*)&Bs[p][kk][tx << 2];
            unsigned long long d0 = dup2_(bv.s[0]), d1 = dup2_(bv.s[1]);
            unsigned long long d2 = dup2_(bv.s[2]), d3 = dup2_(bv.s[3]);
            #pragma unroll
            for (int q = 0; q < MI / 4; ++q) {
                F4U av; av.f = *(float4*)&As[p][kk][ty * MI + q * 4];
                acc2[2*q  ][0] = ffma2_(av.u[0], d0, acc2[2*q  ][0]);
                acc2[2*q+1][0] = ffma2_(av.u[1], d0, acc2[2*q+1][0]);
                acc2[2*q  ][1] = ffma2_(av.u[0], d1, acc2[2*q  ][1]);
                acc2[2*q+1][1] = ffma2_(av.u[1], d1, acc2[2*q+1][1]);
                acc2[2*q  ][2] = ffma2_(av.u[0], d2, acc2[2*q  ][2]);
                acc2[2*q+1][2] = ffma2_(av.u[1], d2, acc2[2*q+1][2]);
                acc2[2*q  ][3] = ffma2_(av.u[0], d3, acc2[2*q  ][3]);
                acc2[2*q+1][3] = ffma2_(av.u[1], d3, acc2[2*q+1][3]);
            }
        }
        if (more) { storeA(p ^ 1); storeB(p ^ 1); __syncthreads(); p ^= 1; }
    }

    // acc2[pr] holds m-offsets (2pr, 2pr+1) relative to ty*MI (pairs from the
    // float4 halves); epilogue enumerates m = m0 + ty*MI + pr*2 + h2.
    #pragma unroll
    for (int pr = 0; pr < MI / 2; ++pr) {
        #pragma unroll
        for (int h2 = 0; h2 < 2; ++h2) {
            int m = m0 + ty * MI + pr * 2 + h2;
            #pragma unroll
            for (int jx = 0; jx < 4; ++jx) {
                int n = n0 + (tx << 2) + jx;
                U2F uv; uv.u = acc2[pr][jx];
                float v = (h2 ? uv.f.y : uv.f.x) * scale;
                size_t idx = (size_t)m * N + n;
                if (ATOMIC) {
                    atomicAdd(&P0[idx], v);
                } else if (EPI == 0) {
                    P0[idx] = v;
                } else if (EPI == 1) {          // O -> ys, err = O - target
                    P0[idx] = v;
                    P1[idx] = v - Q0[idx];
                } else {                        // c = L * (1 - hnew^2)
                    float h = Q0[idx];
                    P0[idx] = v * (1.f - h * h);
                }
            }
        }
    }
}

// ---------------------------------------------------------------------------
// Launch sequence (graph-capturable: kernel launches only)
// ---------------------------------------------------------------------------
extern "C" void kernel_launch(void* const* d_in, const int* in_sizes, int n_in,
                              void* d_out, int out_size)
{
    const float* x      = (const float*)d_in[0];  // [T,B,I]
    const float* target = (const float*)d_in[1];  // [T,B,O]
    const float* h0     = (const float*)d_in[2];  // [B,H]
    const float* W_in   = (const float*)d_in[3];  // [H,I]
    const float* W_hh   = (const float*)d_in[4];  // [H,H]
    const float* W_out  = (const float*)d_in[5];  // [O,H]

    float* out   = (float*)d_out;
    float* ys    = out;                                   // [T*B, O]
    float* hf    = out + (size_t)MROWS * Oo;              // [B,H]
    float* gwout = hf + BH;                               // [O,H]
    float* gwih  = gwout + (size_t)Oo * Hh;               // [H,I]
    float* gwhh  = gwih + (size_t)Hh * Ii;                // [H,H]

    float *p_xin, *p_h, *p_err, *p_c;
    cudaGetSymbolAddress((void**)&p_xin, g_xin);
    cudaGetSymbolAddress((void**)&p_h,   g_h);
    cudaGetSymbolAddress((void**)&p_err, g_err);
    cudaGetSymbolAddress((void**)&p_c,   g_c);

    // 0. zero ys + split-K targets + barriers + h_all[0] (one kernel)
    // (kNumZero, NOT "NZERO": glibc <limits.h> defines NZERO=20 on the GPU host)
    const int kNumZero = Oo * Hh + Hh * Ii + Hh * Hh;   // gwout..gwhh contiguous
    setup_kernel<<<256, 256>>>(ys, MROWS * Oo, gwout, kNumZero, h0);

    // 1. Xin = X @ W_in^T            [4096,1024], K=256  (DOT)
    gemmT<128, true, true, 0, false><<<dim3(Hh / 64, MROWS / 128, 1), 256>>>(
        x, Ii, 1, W_in, Ii, 1, Hh, Ii, 1.f, p_xin, nullptr, nullptr);

    // 2. forward scan (persistent, 4 batch-groups x 32 slices, 256 thr)
    scan_fwd<<<128, 256>>>(W_hh, hf);

    // 3. O = Hnew @ W_out^T -> ys    [4096,128], K=1024, split 4 -> 512 CTAs
    gemmT<64, true, true, 0, true><<<dim3(Oo / 64, MROWS / 64, 4), 256>>>(
        p_h + BH, Hh, 1, W_out, Hh, 1, Oo, Hh / 4, 1.f, ys, nullptr, nullptr);

    // 4. err = ys - target (elementwise)
    err_kernel<<<(MROWS * Oo) / 256, 256>>>(ys, target);

    // 5. c = (err @ W_out) * (1 - hnew^2)                [4096,1024], K=128 (NN)
    gemmT<128, true, false, 2, false><<<dim3(Hh / 64, MROWS / 128, 1), 256>>>(
        p_err, Oo, 1, W_out, 1, Hh, Hh, Oo, 1.f, p_c, nullptr, p_h + BH);

    // 6. backward scan: c -> a (in place)
    scan_bwd<<<BH / 256, 256>>>(W_hh);

    // 7. g_wout = (1/B) * err^T @ Hnew       [128,1024], K=4096, split 16 -> 256 CTAs
    gemmT<128, false, false, 0, true><<<dim3(Hh / 64, Oo / 128, 16), 256>>>(
        p_err, 1, Oo, p_h + BH, 1, Hh, Hh, MROWS / 16, 1.f / Bb, gwout, nullptr, nullptr);

    // 8. g_wih = (1e-3/B) * a^T @ X          [1024,256], K=4096, split 8 -> 256 CTAs
    gemmT<128, false, false, 0, true><<<dim3(Ii / 64, Hh / 128, 8), 256>>>(
        p_c, 1, Hh, x, 1, Ii, Ii, MROWS / 8, 1e-3f / Bb, gwih, nullptr, nullptr);

    // 9. g_whh = (1e-5/B) * a^T @ Hprev      [1024,1024], K=4096, split 4 -> 512 CTAs
    gemmT<128, false, false, 0, true><<<dim3(Hh / 64, Hh / 128, 4), 256>>>(
        p_c, 1, Hh, p_h, 1, Hh, Hh, MROWS / 4, 1e-5f / Bb, gwhh, nullptr, nullptr);
}